// round 4
// baseline (speedup 1.0000x reference)
#include <cuda_runtime.h>
#include <cuda_bf16.h>
#include <cstdint>

// ---------------------------------------------------------------------------
// Speculative-decode cache-loc compaction.
//   span[b]      = accept_length[b] + 1
//   old_start[b] = exclusive_cumsum(span)[b]
//   new_start[b] = exclusive_cumsum(accept_length_filter)[b]
//   out[new_start[b] + i] = tgt_cache_loc[old_start[b] + i],  i < filter[b]
//
// Kernel 1: single-pass decoupled-lookback scan over both sequences,
//           emitting packed per-batch {old_start, new_start, len}.
// Kernel 2: warp-per-batch copy with dst-aligned float4 stores.
// ---------------------------------------------------------------------------

#define MAXB (1 << 17)
#define SCAN_BLK 1024
#define MAX_TILES 128          // MAXB / SCAN_BLK

// Packed tile state: [61:60] flag (0=invalid, 1=aggregate, 2=inclusive),
//                    [59:30] span sum, [29:0] filter sum. Sums < 2^27.
__device__ unsigned long long g_tile_state[MAX_TILES];   // zero-init at load
__device__ unsigned int g_done;                          // zero-init at load
__device__ int4 g_meta[MAXB];  // {old_start, new_start, len, pad}

__device__ __forceinline__ int warp_incl_scan(int v, int lane) {
    #pragma unroll
    for (int off = 1; off < 32; off <<= 1) {
        int n = __shfl_up_sync(0xFFFFFFFFu, v, off);
        if (lane >= off) v += n;
    }
    return v;
}

__device__ __forceinline__ unsigned long long pack_state(unsigned long long flag,
                                                         int s, int f) {
    return (flag << 60) | ((unsigned long long)(unsigned)s << 30)
         | (unsigned long long)(unsigned)f;
}

// ---- kernel 1: fused single-pass scan -------------------------------------
__global__ void __launch_bounds__(SCAN_BLK)
k_scan_fused(const int* __restrict__ al, const int* __restrict__ alf, int B) {
    const int tid = threadIdx.x;
    const int tile = blockIdx.x;
    const int i = tile * SCAN_BLK + tid;
    const int lane = tid & 31, wid = tid >> 5;

    int s = 0, f = 0;
    if (i < B) { s = al[i] + 1; f = alf[i]; }

    int incl_s = warp_incl_scan(s, lane);
    int incl_f = warp_incl_scan(f, lane);

    __shared__ int ws[32], wf[32], wso[32], wfo[32];
    __shared__ int sh_tot[2];
    __shared__ int sh_ex[2];
    if (lane == 31) { ws[wid] = incl_s; wf[wid] = incl_f; }
    __syncthreads();
    if (wid == 0) {
        int vs = ws[lane], vf = wf[lane];
        int is  = warp_incl_scan(vs, lane);
        int iff = warp_incl_scan(vf, lane);
        wso[lane] = is - vs;            // exclusive warp offsets within block
        wfo[lane] = iff - vf;
        if (lane == 31) { sh_tot[0] = is; sh_tot[1] = iff; }
    }
    __syncthreads();
    const int ts = sh_tot[0], tf = sh_tot[1];

    // warp 0: publish aggregate, decoupled lookback, publish inclusive
    if (wid == 0) {
        if (lane == 0)
            atomicExch(&g_tile_state[tile], pack_state(1ULL, ts, tf));

        int es = 0, ef = 0;
        int idx = tile - 1;
        while (idx >= 0) {
            int p = idx - lane;            // lane 0 = closest predecessor
            bool active = (p >= 0);
            unsigned long long st = 0;
            if (active) {
                do {
                    st = *(volatile unsigned long long*)&g_tile_state[p];
                } while ((st >> 60) == 0ULL);
            }
            unsigned incl_mask =
                __ballot_sync(0xFFFFFFFFu, active && ((st >> 60) == 2ULL));
            int L = incl_mask ? (__ffs(incl_mask) - 1) : 32;
            int cs = 0, cf = 0;
            if (active && lane <= L) {
                cs = (int)((st >> 30) & 0x3FFFFFFFULL);
                cf = (int)(st & 0x3FFFFFFFULL);
            }
            #pragma unroll
            for (int o = 16; o > 0; o >>= 1) {
                cs += __shfl_xor_sync(0xFFFFFFFFu, cs, o);
                cf += __shfl_xor_sync(0xFFFFFFFFu, cf, o);
            }
            es += cs; ef += cf;
            if (L < 32) break;             // hit an INCLUSIVE record
            idx -= 32;
        }
        if (lane == 0) {
            atomicExch(&g_tile_state[tile], pack_state(2ULL, es + ts, ef + tf));
            sh_ex[0] = es; sh_ex[1] = ef;
        }
    }
    __syncthreads();
    const int es = sh_ex[0], ef = sh_ex[1];

    if (i < B) {
        int os = es + (incl_s - s) + wso[wid];
        int ns = ef + (incl_f - f) + wfo[wid];
        g_meta[i] = make_int4(os, ns, f, 0);
    }

    // Reset tile state for the next (graph-replayed) launch. Safe: each block
    // increments g_done only AFTER its lookback is complete, so when the count
    // reaches gridDim.x no block will ever read g_tile_state again this launch.
    if (tid == 0) {
        __threadfence();
        unsigned pos = atomicAdd(&g_done, 1u);
        if (pos == gridDim.x - 1) {
            for (int t2 = 0; t2 < (int)gridDim.x; t2++)
                g_tile_state[t2] = 0ULL;
            __threadfence();
            g_done = 0;
        }
    }
}

// ---- kernel 2: warp-per-batch copy, dst-aligned float4 --------------------
__global__ void __launch_bounds__(256)
k_copy(const float* __restrict__ src, float* __restrict__ out, int B) {
    int gwarp = (blockIdx.x * blockDim.x + threadIdx.x) >> 5;
    int lane = threadIdx.x & 31;
    if (gwarp >= B) return;

    int4 m = __ldg(&g_meta[gwarp]);     // one broadcast LDG.128
    int len = m.z;
    if (len == 0) return;
    int os = m.x, ns = m.y;

    // head: bring dst to 16B alignment
    int head = (4 - (ns & 3)) & 3;
    if (head > len) head = len;
    if (lane < head) out[ns + lane] = __ldg(&src[os + lane]);

    int rem = len - head;
    int nb = rem >> 2;                   // number of float4 groups
    const float* s2 = src + os + head;
    float4* d4 = reinterpret_cast<float4*>(out + ns + head);

    if ((((uintptr_t)s2) & 15) == 0) {
        // src co-aligned: full 16B loads + 16B stores
        const float4* s4 = reinterpret_cast<const float4*>(s2);
        for (int g = lane; g < nb; g += 32)
            d4[g] = __ldg(&s4[g]);
    } else {
        // src misaligned: 4 independent scalar loads, one 16B store
        for (int g = lane; g < nb; g += 32) {
            float4 v;
            v.x = __ldg(s2 + 4 * g + 0);
            v.y = __ldg(s2 + 4 * g + 1);
            v.z = __ldg(s2 + 4 * g + 2);
            v.w = __ldg(s2 + 4 * g + 3);
            d4[g] = v;
        }
    }

    int t = head + (nb << 2) + lane;
    if (t < len) out[ns + t] = __ldg(&src[os + t]);
}

// ---------------------------------------------------------------------------
extern "C" void kernel_launch(void* const* d_in, const int* in_sizes, int n_in,
                              void* d_out, int out_size) {
    const float* tgt = (const float*)d_in[0];
    const int* al  = (const int*)d_in[1];
    const int* alf = (const int*)d_in[2];
    float* out = (float*)d_out;

    int B = in_sizes[1];
    int ntiles = (B + SCAN_BLK - 1) / SCAN_BLK;   // 64 for B=65536

    k_scan_fused<<<ntiles, SCAN_BLK>>>(al, alf, B);

    long long total_threads = (long long)B * 32;
    int tpb = 256;
    int cblocks = (int)((total_threads + tpb - 1) / tpb);
    k_copy<<<cblocks, tpb>>>(tgt, out, B);
}